// round 8
// baseline (speedup 1.0000x reference)
#include <cuda_runtime.h>

// Problem constants (fixed shapes from reference):
//   x : (2, 128, 96, 96) f32, w{q,k,v} : (4, 32, 32) f32
//   K = 5 window, reflect pad 2, G = 4 groups of 32 channels.
#define BB   2
#define GG   4
#define CIN  32
#define CON  32
#define HHN  96
#define WWN  96
#define HWSZ (HHN * WWN)
#define CTOT 128

// Scratch for the three 1x1-conv outputs (q, k, v), each (B, 128, 96, 96).
__device__ __align__(256) float g_q[BB * CTOT * HWSZ];
__device__ __align__(256) float g_k[BB * CTOT * HWSZ];
__device__ __align__(256) float g_v[BB * CTOT * HWSZ];

// -----------------------------------------------------------------------------
// Kernel A: grouped 1x1 convs (q, k, v) fused.
// One CTA per (b, g, h, w-half): 1536 CTAs of 256 threads. Each thread owns
// one output channel and a 6-pixel w segment (18 scalar accumulators, ~45
// regs) -> occupancy ~6 CTAs/SM (vs 2 with the old 36-accumulator tile),
// pushing the fma pipe toward its 23.9k-cycle chip floor for 226M FMA.
// Scalar FFMA mainloop (the f32x2 path measurably regressed on this
// toolchain), direct global stores (store-pattern was proven non-binding).
// -----------------------------------------------------------------------------
#define WHALF 48

__global__ __launch_bounds__(256) void qkv_kernel(
    const float* __restrict__ x,
    const float* __restrict__ wq,
    const float* __restrict__ wk,
    const float* __restrict__ wv)
{
    __shared__ float xs[CIN * WHALF];          // 6 KB input half-row tile
    __shared__ float wqs[CON * 33];            // padded stride 33
    __shared__ float wks[CON * 33];
    __shared__ float wvs[CON * 33];

    const int h     = blockIdx.x;
    const int bg    = blockIdx.y;              // b*G + g
    const int whalf = blockIdx.z;              // 0 or 1
    const int g     = bg & (GG - 1);
    const int tid   = threadIdx.x;

    // Stage x half-row with float4 loads: x[bg*32 + i][h][whalf*48 + w]
    const float* xbase = x + (size_t)bg * CIN * HWSZ + (size_t)h * WWN + whalf * WHALF;
    #pragma unroll
    for (int idx = tid; idx < CIN * (WHALF / 4); idx += 256) {
        int i  = idx / (WHALF / 4);
        int w4 = idx - i * (WHALF / 4);
        reinterpret_cast<float4*>(xs)[idx] =
            reinterpret_cast<const float4*>(xbase + (size_t)i * HWSZ)[w4];
    }
    // Stage weights of this group
    const float* wqg = wq + (size_t)g * CON * CIN;
    const float* wkg = wk + (size_t)g * CON * CIN;
    const float* wvg = wv + (size_t)g * CON * CIN;
    #pragma unroll
    for (int idx = tid; idx < CON * CIN; idx += 256) {
        int o = idx >> 5;
        int i = idx & 31;
        wqs[o * 33 + i] = wqg[idx];
        wks[o * 33 + i] = wkg[idx];
        wvs[o * 33 + i] = wvg[idx];
    }
    __syncthreads();

    const int o    = tid >> 3;            // 0..31 output channel
    const int wseg = (tid & 7) * 6;       // 6 consecutive w positions

    float aq[6], ak[6], av[6];
    #pragma unroll
    for (int u = 0; u < 6; u++) { aq[u] = 0.f; ak[u] = 0.f; av[u] = 0.f; }

    #pragma unroll 8
    for (int i = 0; i < CIN; i++) {
        const float wqv = wqs[o * 33 + i];
        const float wkv = wks[o * 33 + i];
        const float wvv = wvs[o * 33 + i];
        const float2* xv = reinterpret_cast<const float2*>(&xs[i * WHALF + wseg]);
        float2 x0 = xv[0], x1 = xv[1], x2 = xv[2];
        float xr[6] = { x0.x, x0.y, x1.x, x1.y, x2.x, x2.y };
        #pragma unroll
        for (int u = 0; u < 6; u++) {
            aq[u] = fmaf(xr[u], wqv, aq[u]);
            ak[u] = fmaf(xr[u], wkv, ak[u]);
            av[u] = fmaf(xr[u], wvv, av[u]);
        }
    }

    const size_t obase = (size_t)(bg * CON + o) * HWSZ
                       + (size_t)h * WWN + whalf * WHALF + wseg;
    float2* qo = reinterpret_cast<float2*>(&g_q[obase]);
    float2* ko = reinterpret_cast<float2*>(&g_k[obase]);
    float2* vo = reinterpret_cast<float2*>(&g_v[obase]);
    #pragma unroll
    for (int u = 0; u < 3; u++) {
        qo[u] = make_float2(aq[2*u], aq[2*u+1]);
        ko[u] = make_float2(ak[2*u], ak[2*u+1]);
        vo[u] = make_float2(av[2*u], av[2*u+1]);
    }
}

// -----------------------------------------------------------------------------
// Kernel B: per-channel 5x5 windowed softmax with reflect indexing.
// One CTA = 32x32 spatial tile x 1 channel. Each thread computes 4 consecutive
// w outputs (adjacent windows share 4/5 columns -> 20 LDS/output).
// Halo stride 41 keeps scalar LDS conflict-free. Single-pass softmax via raw
// ex2.approx (log2e folded into q). Runs within ~25% of the MUFU chip floor.
// -----------------------------------------------------------------------------
__device__ __forceinline__ int refl(int i, int n) {
    return i < 0 ? -i : (i >= n ? 2 * n - 2 - i : i);
}

__device__ __forceinline__ float ex2(float x) {
    float y;
    asm("ex2.approx.ftz.f32 %0, %1;" : "=f"(y) : "f"(x));
    return y;
}

#define HALO 36
#define HSTR 41

__global__ __launch_bounds__(256) void attn_kernel(float* __restrict__ out)
{
    __shared__ float ks[HALO * HSTR];   // 5.9 KB
    __shared__ float vs[HALO * HSTR];

    const int ch  = blockIdx.z;               // 0..255 = b*128 + channel
    const int h0  = blockIdx.y * 32;
    const int w0  = blockIdx.x * 32;
    const int tid = threadIdx.x;
    const int tx  = tid & 7;                  // 8 threads across w (4 outputs each)
    const int ty  = tid >> 3;                 // 32 rows

    const size_t cbase = (size_t)ch * HWSZ;

    // Stage k/v halos (36x36 window, reflect at global borders).
    #pragma unroll
    for (int idx = tid; idx < HALO * HALO; idx += 256) {
        int r  = idx / HALO;
        int c  = idx - r * HALO;
        int hh = refl(h0 - 2 + r, HHN);
        int ww = refl(w0 - 2 + c, WWN);
        size_t gi = cbase + (size_t)hh * WWN + ww;
        ks[r * HSTR + c] = g_k[gi];
        vs[r * HSTR + c] = g_v[gi];
    }
    __syncthreads();

    const int h    = h0 + ty;
    const int wsub = tx * 4;                  // halo column base for this thread
    const size_t pix = (size_t)h * WWN + (w0 + wsub);

    const float4 q4 = *reinterpret_cast<const float4*>(&g_q[cbase + pix]);
    const float L2E = 1.44269504088896341f;
    float ql2[4] = { q4.x * L2E, q4.y * L2E, q4.z * L2E, q4.w * L2E };

    float num[4] = {0.f, 0.f, 0.f, 0.f};
    float den[4] = {0.f, 0.f, 0.f, 0.f};

    #pragma unroll
    for (int r = 0; r < 5; r++) {
        const float* kp = &ks[(ty + r) * HSTR + wsub];
        const float* vp = &vs[(ty + r) * HSTR + wsub];
        float kk[8], vv[8];
        #pragma unroll
        for (int j = 0; j < 8; j++) { kk[j] = kp[j]; vv[j] = vp[j]; }
        #pragma unroll
        for (int o = 0; o < 4; o++) {
            #pragma unroll
            for (int c = 0; c < 5; c++) {
                float e = ex2(ql2[o] * kk[o + c]);
                den[o] += e;
                num[o] = fmaf(e, vv[o + c], num[o]);
            }
        }
    }

    float4 r4 = make_float4(__fdividef(num[0], den[0]),
                            __fdividef(num[1], den[1]),
                            __fdividef(num[2], den[2]),
                            __fdividef(num[3], den[3]));
    *reinterpret_cast<float4*>(&out[cbase + pix]) = r4;
}

// -----------------------------------------------------------------------------
// Launch: two kernels, graph-capturable (no sync, no alloc).
// Inputs (metadata order): x, wq, wk, wv — all float32. Output float32.
// -----------------------------------------------------------------------------
extern "C" void kernel_launch(void* const* d_in, const int* in_sizes, int n_in,
                              void* d_out, int out_size)
{
    const float* x  = (const float*)d_in[0];
    const float* wq = (const float*)d_in[1];
    const float* wk = (const float*)d_in[2];
    const float* wv = (const float*)d_in[3];
    float* out = (float*)d_out;

    qkv_kernel<<<dim3(HHN, BB * GG, 2), 256>>>(x, wq, wk, wv);
    attn_kernel<<<dim3(WWN / 32, HHN / 32, BB * CTOT), dim3(256)>>>(out);
}

// round 9
// speedup vs baseline: 1.0361x; 1.0361x over previous
#include <cuda_runtime.h>

// Problem constants (fixed shapes from reference):
//   x : (2, 128, 96, 96) f32, w{q,k,v} : (4, 32, 32) f32
//   K = 5 window, reflect pad 2, G = 4 groups of 32 channels.
#define BB   2
#define GG   4
#define CIN  32
#define CON  32
#define HHN  96
#define WWN  96
#define HWSZ (HHN * WWN)
#define CTOT 128

// Scratch for the three 1x1-conv outputs (q, k, v), each (B, 128, 96, 96).
__device__ __align__(256) float g_q[BB * CTOT * HWSZ];
__device__ __align__(256) float g_k[BB * CTOT * HWSZ];
__device__ __align__(256) float g_v[BB * CTOT * HWSZ];

// -----------------------------------------------------------------------------
// Kernel A: grouped 1x1 convs (q, k, v) fused — one CTA per (b, g, h) row.
// EXACT restore of the best measured variant (R4, 16.3us): 36 scalar-FFMA
// accumulators per thread (36 FMA per 6 LDS keeps the fma pipe fed),
// __launch_bounds__(256,2) for 2 resident CTAs, direct strided stores.
// Measured ledger: f32x2 mainloop, smem-bounce epilogue, and small-tile/
// high-occupancy variants ALL regressed this kernel.
// -----------------------------------------------------------------------------
__global__ __launch_bounds__(256, 2) void qkv_kernel(
    const float* __restrict__ x,
    const float* __restrict__ wq,
    const float* __restrict__ wk,
    const float* __restrict__ wv)
{
    __shared__ float xs[CIN * WWN];            // 12 KB
    __shared__ float wqs[CON * 33];            // padded stride 33
    __shared__ float wks[CON * 33];
    __shared__ float wvs[CON * 33];

    const int h   = blockIdx.x;
    const int bg  = blockIdx.y;                // b*G + g
    const int g   = bg & (GG - 1);
    const int tid = threadIdx.x;

    // Stage x row: x[bg*32 + i][h][w]
    const float* xbase = x + (size_t)bg * CIN * HWSZ + (size_t)h * WWN;
    #pragma unroll
    for (int idx = tid; idx < CIN * (WWN / 4); idx += 256) {
        int i  = idx / (WWN / 4);
        int w4 = idx - i * (WWN / 4);
        reinterpret_cast<float4*>(xs)[i * (WWN / 4) + w4] =
            reinterpret_cast<const float4*>(xbase + (size_t)i * HWSZ)[w4];
    }
    // Stage weights of this group
    const float* wqg = wq + (size_t)g * CON * CIN;
    const float* wkg = wk + (size_t)g * CON * CIN;
    const float* wvg = wv + (size_t)g * CON * CIN;
    #pragma unroll
    for (int idx = tid; idx < CON * CIN; idx += 256) {
        int o = idx >> 5;
        int i = idx & 31;
        wqs[o * 33 + i] = wqg[idx];
        wks[o * 33 + i] = wkg[idx];
        wvs[o * 33 + i] = wvg[idx];
    }
    __syncthreads();

    const int o    = tid >> 3;            // 0..31 output channel
    const int wseg = (tid & 7) * 12;      // 12 consecutive w positions

    float aq[12], ak[12], av[12];
    #pragma unroll
    for (int u = 0; u < 12; u++) { aq[u] = 0.f; ak[u] = 0.f; av[u] = 0.f; }

    #pragma unroll 8
    for (int i = 0; i < CIN; i++) {
        const float wqv = wqs[o * 33 + i];
        const float wkv = wks[o * 33 + i];
        const float wvv = wvs[o * 33 + i];
        const float4* xv = reinterpret_cast<const float4*>(&xs[i * WWN + wseg]);
        float4 x0 = xv[0], x1 = xv[1], x2 = xv[2];
        float xr[12] = { x0.x, x0.y, x0.z, x0.w,
                         x1.x, x1.y, x1.z, x1.w,
                         x2.x, x2.y, x2.z, x2.w };
        #pragma unroll
        for (int u = 0; u < 12; u++) {
            aq[u] = fmaf(xr[u], wqv, aq[u]);
            ak[u] = fmaf(xr[u], wkv, ak[u]);
            av[u] = fmaf(xr[u], wvv, av[u]);
        }
    }

    const size_t obase = (size_t)(bg * CON + o) * HWSZ + (size_t)h * WWN + wseg;
    float4* qo = reinterpret_cast<float4*>(&g_q[obase]);
    float4* ko = reinterpret_cast<float4*>(&g_k[obase]);
    float4* vo = reinterpret_cast<float4*>(&g_v[obase]);
    #pragma unroll
    for (int u = 0; u < 3; u++) {
        qo[u] = make_float4(aq[4*u], aq[4*u+1], aq[4*u+2], aq[4*u+3]);
        ko[u] = make_float4(ak[4*u], ak[4*u+1], ak[4*u+2], ak[4*u+3]);
        vo[u] = make_float4(av[4*u], av[4*u+1], av[4*u+2], av[4*u+3]);
    }
}

// -----------------------------------------------------------------------------
// Kernel B: per-channel 5x5 windowed softmax with reflect indexing.
// One CTA = 32x32 spatial tile x 1 channel, 128 threads (4 tx x 32 ty).
// Each thread computes 8 consecutive w outputs: adjacent windows share 4/5
// columns, so 12 k + 12 v smem loads per window row serve 8 outputs
// (15 LDS/output vs 20 before) and per-output loop/address overhead halves —
// raising MUFU saturation (hard floor ~13.8us for 59M exps).
// Bank check: addr = 41*(ty+r) + 8*tx + j -> bank 9*ty + 8*tx + j mod 32 is
// injective over the warp's 8(ty) x 4(tx) lanes: conflict-free scalar LDS.
// Single-pass softmax via raw ex2.approx (log2e folded into q).
// -----------------------------------------------------------------------------
__device__ __forceinline__ int refl(int i, int n) {
    return i < 0 ? -i : (i >= n ? 2 * n - 2 - i : i);
}

__device__ __forceinline__ float ex2(float x) {
    float y;
    asm("ex2.approx.ftz.f32 %0, %1;" : "=f"(y) : "f"(x));
    return y;
}

#define HALO 36
#define HSTR 41

__global__ __launch_bounds__(128) void attn_kernel(float* __restrict__ out)
{
    __shared__ float ks[HALO * HSTR];   // 5.9 KB
    __shared__ float vs[HALO * HSTR];

    const int ch  = blockIdx.z;               // 0..255 = b*128 + channel
    const int h0  = blockIdx.y * 32;
    const int w0  = blockIdx.x * 32;
    const int tid = threadIdx.x;
    const int tx  = tid & 3;                  // 4 threads across w (8 outputs each)
    const int ty  = tid >> 2;                 // 32 rows

    const size_t cbase = (size_t)ch * HWSZ;

    // Stage k/v halos (36x36 window, reflect at global borders).
    for (int idx = tid; idx < HALO * HALO; idx += 128) {
        int r  = idx / HALO;
        int c  = idx - r * HALO;
        int hh = refl(h0 - 2 + r, HHN);
        int ww = refl(w0 - 2 + c, WWN);
        size_t gi = cbase + (size_t)hh * WWN + ww;
        ks[r * HSTR + c] = g_k[gi];
        vs[r * HSTR + c] = g_v[gi];
    }
    __syncthreads();

    const int h    = h0 + ty;
    const int wsub = tx * 8;                  // halo column base for this thread
    const size_t pix = (size_t)h * WWN + (w0 + wsub);

    const float4 qa = *reinterpret_cast<const float4*>(&g_q[cbase + pix]);
    const float4 qb = *reinterpret_cast<const float4*>(&g_q[cbase + pix + 4]);
    const float L2E = 1.44269504088896341f;
    float ql2[8] = { qa.x * L2E, qa.y * L2E, qa.z * L2E, qa.w * L2E,
                     qb.x * L2E, qb.y * L2E, qb.z * L2E, qb.w * L2E };

    float num[8], den[8];
    #pragma unroll
    for (int o = 0; o < 8; o++) { num[o] = 0.f; den[o] = 0.f; }

    #pragma unroll
    for (int r = 0; r < 5; r++) {
        const float* kp = &ks[(ty + r) * HSTR + wsub];
        const float* vp = &vs[(ty + r) * HSTR + wsub];
        float kk[12], vv[12];
        #pragma unroll
        for (int j = 0; j < 12; j++) { kk[j] = kp[j]; vv[j] = vp[j]; }
        #pragma unroll
        for (int o = 0; o < 8; o++) {
            #pragma unroll
            for (int c = 0; c < 5; c++) {
                float e = ex2(ql2[o] * kk[o + c]);
                den[o] += e;
                num[o] = fmaf(e, vv[o + c], num[o]);
            }
        }
    }

    float4 ra = make_float4(__fdividef(num[0], den[0]),
                            __fdividef(num[1], den[1]),
                            __fdividef(num[2], den[2]),
                            __fdividef(num[3], den[3]));
    float4 rb = make_float4(__fdividef(num[4], den[4]),
                            __fdividef(num[5], den[5]),
                            __fdividef(num[6], den[6]),
                            __fdividef(num[7], den[7]));
    *reinterpret_cast<float4*>(&out[cbase + pix])     = ra;
    *reinterpret_cast<float4*>(&out[cbase + pix + 4]) = rb;
}

// -----------------------------------------------------------------------------
// Launch: two kernels, graph-capturable (no sync, no alloc).
// Inputs (metadata order): x, wq, wk, wv — all float32. Output float32.
// -----------------------------------------------------------------------------
extern "C" void kernel_launch(void* const* d_in, const int* in_sizes, int n_in,
                              void* d_out, int out_size)
{
    const float* x  = (const float*)d_in[0];
    const float* wq = (const float*)d_in[1];
    const float* wk = (const float*)d_in[2];
    const float* wv = (const float*)d_in[3];
    float* out = (float*)d_out;

    qkv_kernel<<<dim3(HHN, BB * GG), 256>>>(x, wq, wk, wv);
    attn_kernel<<<dim3(WWN / 32, HHN / 32, BB * CTOT), dim3(128)>>>(out);
}

// round 10
// speedup vs baseline: 1.1557x; 1.1154x over previous
#include <cuda_runtime.h>

// Problem constants (fixed shapes from reference):
//   x : (2, 128, 96, 96) f32, w{q,k,v} : (4, 32, 32) f32
//   K = 5 window, reflect pad 2, G = 4 groups of 32 channels.
#define BB   2
#define GG   4
#define CIN  32
#define CON  32
#define HHN  96
#define WWN  96
#define HWSZ (HHN * WWN)
#define CTOT 128

// Scratch for the three 1x1-conv outputs (q, k, v), each (B, 128, 96, 96).
__device__ __align__(256) float g_q[BB * CTOT * HWSZ];
__device__ __align__(256) float g_k[BB * CTOT * HWSZ];
__device__ __align__(256) float g_v[BB * CTOT * HWSZ];

// -----------------------------------------------------------------------------
// Kernel A: grouped 1x1 convs (q, k, v) fused — one CTA per (b, g, h) row.
// Best measured variant: 36 scalar-FFMA accumulators per thread (36 FMA per
// 6 LDS keeps the fma pipe fed), __launch_bounds__(256,2), direct stores.
// Measured ledger: f32x2 mainloop, smem-bounce epilogue, and small-tile/
// high-occupancy variants ALL regressed this kernel. Do not touch.
// -----------------------------------------------------------------------------
__global__ __launch_bounds__(256, 2) void qkv_kernel(
    const float* __restrict__ x,
    const float* __restrict__ wq,
    const float* __restrict__ wk,
    const float* __restrict__ wv)
{
    __shared__ float xs[CIN * WWN];            // 12 KB
    __shared__ float wqs[CON * 33];            // padded stride 33
    __shared__ float wks[CON * 33];
    __shared__ float wvs[CON * 33];

    const int h   = blockIdx.x;
    const int bg  = blockIdx.y;                // b*G + g
    const int g   = bg & (GG - 1);
    const int tid = threadIdx.x;

    // Stage x row: x[bg*32 + i][h][w]
    const float* xbase = x + (size_t)bg * CIN * HWSZ + (size_t)h * WWN;
    #pragma unroll
    for (int idx = tid; idx < CIN * (WWN / 4); idx += 256) {
        int i  = idx / (WWN / 4);
        int w4 = idx - i * (WWN / 4);
        reinterpret_cast<float4*>(xs)[i * (WWN / 4) + w4] =
            reinterpret_cast<const float4*>(xbase + (size_t)i * HWSZ)[w4];
    }
    // Stage weights of this group
    const float* wqg = wq + (size_t)g * CON * CIN;
    const float* wkg = wk + (size_t)g * CON * CIN;
    const float* wvg = wv + (size_t)g * CON * CIN;
    #pragma unroll
    for (int idx = tid; idx < CON * CIN; idx += 256) {
        int o = idx >> 5;
        int i = idx & 31;
        wqs[o * 33 + i] = wqg[idx];
        wks[o * 33 + i] = wkg[idx];
        wvs[o * 33 + i] = wvg[idx];
    }
    __syncthreads();

    const int o    = tid >> 3;            // 0..31 output channel
    const int wseg = (tid & 7) * 12;      // 12 consecutive w positions

    float aq[12], ak[12], av[12];
    #pragma unroll
    for (int u = 0; u < 12; u++) { aq[u] = 0.f; ak[u] = 0.f; av[u] = 0.f; }

    #pragma unroll 8
    for (int i = 0; i < CIN; i++) {
        const float wqv = wqs[o * 33 + i];
        const float wkv = wks[o * 33 + i];
        const float wvv = wvs[o * 33 + i];
        const float4* xv = reinterpret_cast<const float4*>(&xs[i * WWN + wseg]);
        float4 x0 = xv[0], x1 = xv[1], x2 = xv[2];
        float xr[12] = { x0.x, x0.y, x0.z, x0.w,
                         x1.x, x1.y, x1.z, x1.w,
                         x2.x, x2.y, x2.z, x2.w };
        #pragma unroll
        for (int u = 0; u < 12; u++) {
            aq[u] = fmaf(xr[u], wqv, aq[u]);
            ak[u] = fmaf(xr[u], wkv, ak[u]);
            av[u] = fmaf(xr[u], wvv, av[u]);
        }
    }

    const size_t obase = (size_t)(bg * CON + o) * HWSZ + (size_t)h * WWN + wseg;
    float4* qo = reinterpret_cast<float4*>(&g_q[obase]);
    float4* ko = reinterpret_cast<float4*>(&g_k[obase]);
    float4* vo = reinterpret_cast<float4*>(&g_v[obase]);
    #pragma unroll
    for (int u = 0; u < 3; u++) {
        qo[u] = make_float4(aq[4*u], aq[4*u+1], aq[4*u+2], aq[4*u+3]);
        ko[u] = make_float4(ak[4*u], ak[4*u+1], ak[4*u+2], ak[4*u+3]);
        vo[u] = make_float4(av[4*u], av[4*u+1], av[4*u+2], av[4*u+3]);
    }
}

// -----------------------------------------------------------------------------
// Kernel B: per-channel 5x5 windowed softmax with reflect indexing.
// Proven shape: 256 threads (8 tx x 32 ty), 4 consecutive w outputs/thread.
// NEW: halo stride 44 (divisible by 4) so the 8-float k/v runs per window row
// load as 2 x LDS.128 each — 16 scalar LDS -> 4 vector LDS per row, cutting
// ~12% of the dynamic instruction stream (issue port was co-saturated with
// MUFU at 79%). LDS.128 phase check: float4-addr = 11*(ty+r) + tx; each
// 8-lane phase spans tx=0..7 -> 8 distinct residues mod 8 -> conflict-free.
// Single-pass softmax via raw ex2.approx (log2e folded into q).
// -----------------------------------------------------------------------------
__device__ __forceinline__ int refl(int i, int n) {
    return i < 0 ? -i : (i >= n ? 2 * n - 2 - i : i);
}

__device__ __forceinline__ float ex2(float x) {
    float y;
    asm("ex2.approx.ftz.f32 %0, %1;" : "=f"(y) : "f"(x));
    return y;
}

#define HALO 36
#define HSTR 44

__global__ __launch_bounds__(256) void attn_kernel(float* __restrict__ out)
{
    __shared__ __align__(16) float ks[HALO * HSTR];   // 6.3 KB
    __shared__ __align__(16) float vs[HALO * HSTR];

    const int ch  = blockIdx.z;               // 0..255 = b*128 + channel
    const int h0  = blockIdx.y * 32;
    const int w0  = blockIdx.x * 32;
    const int tid = threadIdx.x;
    const int tx  = tid & 7;                  // 8 threads across w (4 outputs each)
    const int ty  = tid >> 3;                 // 32 rows

    const size_t cbase = (size_t)ch * HWSZ;

    // Stage k/v halos (36x36 window, reflect at global borders).
    #pragma unroll
    for (int idx = tid; idx < HALO * HALO; idx += 256) {
        int r  = idx / HALO;
        int c  = idx - r * HALO;
        int hh = refl(h0 - 2 + r, HHN);
        int ww = refl(w0 - 2 + c, WWN);
        size_t gi = cbase + (size_t)hh * WWN + ww;
        ks[r * HSTR + c] = g_k[gi];
        vs[r * HSTR + c] = g_v[gi];
    }
    __syncthreads();

    const int h    = h0 + ty;
    const int wsub = tx * 4;                  // halo column base for this thread
    const size_t pix = (size_t)h * WWN + (w0 + wsub);

    const float4 q4 = *reinterpret_cast<const float4*>(&g_q[cbase + pix]);
    const float L2E = 1.44269504088896341f;
    float ql2[4] = { q4.x * L2E, q4.y * L2E, q4.z * L2E, q4.w * L2E };

    float num[4] = {0.f, 0.f, 0.f, 0.f};
    float den[4] = {0.f, 0.f, 0.f, 0.f};

    #pragma unroll
    for (int r = 0; r < 5; r++) {
        const float4* kp = reinterpret_cast<const float4*>(&ks[(ty + r) * HSTR + wsub]);
        const float4* vp = reinterpret_cast<const float4*>(&vs[(ty + r) * HSTR + wsub]);
        float4 k0 = kp[0], k1 = kp[1];
        float4 v0 = vp[0], v1 = vp[1];
        float kk[8] = { k0.x, k0.y, k0.z, k0.w, k1.x, k1.y, k1.z, k1.w };
        float vv[8] = { v0.x, v0.y, v0.z, v0.w, v1.x, v1.y, v1.z, v1.w };
        #pragma unroll
        for (int o = 0; o < 4; o++) {
            #pragma unroll
            for (int c = 0; c < 5; c++) {
                float e = ex2(ql2[o] * kk[o + c]);
                den[o] += e;
                num[o] = fmaf(e, vv[o + c], num[o]);
            }
        }
    }

    float4 r4 = make_float4(__fdividef(num[0], den[0]),
                            __fdividef(num[1], den[1]),
                            __fdividef(num[2], den[2]),
                            __fdividef(num[3], den[3]));
    *reinterpret_cast<float4*>(&out[cbase + pix]) = r4;
}

// -----------------------------------------------------------------------------
// Launch: two kernels, graph-capturable (no sync, no alloc).
// Inputs (metadata order): x, wq, wk, wv — all float32. Output float32.
// -----------------------------------------------------------------------------
extern "C" void kernel_launch(void* const* d_in, const int* in_sizes, int n_in,
                              void* d_out, int out_size)
{
    const float* x  = (const float*)d_in[0];
    const float* wq = (const float*)d_in[1];
    const float* wk = (const float*)d_in[2];
    const float* wv = (const float*)d_in[3];
    float* out = (float*)d_out;

    qkv_kernel<<<dim3(HHN, BB * GG), 256>>>(x, wq, wk, wv);
    attn_kernel<<<dim3(WWN / 32, HHN / 32, BB * CTOT), dim3(256)>>>(out);
}